// round 16
// baseline (speedup 1.0000x reference)
#include <cuda_runtime.h>
#include <cstdint>
#include <math.h>

#define Bq     16
#define Cq     256
#define HWq    16384
#define INTERq 128
#define CHUNKS 128

// scratch (zero-initialized device globals; counters self-reset each call)
__device__ float g_csum[Bq * CHUNKS * Cq];  // [b][chunk][c] (2 MB)
__device__ float g_pt  [Cq * Bq];           // pooled means [c][b]
__device__ float g_gtp [384 * Bq];          // proj outputs [col][b]: g|theta|phi
__device__ float g_wyt [Cq * Bq];           // pre-BN activations [c][b]
__device__ int   g_idx [Bq * 3];
__device__ int   g_pcnt[Bq];                // per-sample k1 completion counters
__device__ int   g_flag;                    // topk-ready flag
__device__ int   g_fin;                     // gather completion counter

__device__ __forceinline__ float gelu_exact(float v) {
    return 0.5f * v * (1.0f + erff(v * 0.70710678118654752f));
}

// ---------------------------------------------------------------------------
// K1 (R4 body, proven 45.6us @ 75.8% DRAM) + fused per-sample pooling:
//   the last-finishing block of each sample reduces its 128 csum partials
//   (fixed order -> deterministic) and writes g_pt; counter self-resets.
// ---------------------------------------------------------------------------
__global__ __launch_bounds__(256) void k1_stream(const float* __restrict__ x,
                                                 const float* __restrict__ W3,
                                                 float* __restrict__ out) {
    __shared__ float sw[Cq];
    __shared__ float scs[Cq][8];
    __shared__ float sdot[4][32][32];
    __shared__ int   s_last;

    const int b     = blockIdx.x >> 7;
    const int chunk = blockIdx.x & 127;
    const int t  = threadIdx.x;
    const int cw = t >> 3;
    const int pw = t & 7;

    if (t == 0) s_last = 0;

    for (int i = t; i < Cq; i += 256) sw[i] = W3[i];
    __syncthreads();

    const float* xb = x + ((size_t)b * Cq + (size_t)cw * 8) * HWq
                        + (size_t)chunk * 128 + (size_t)pw * 4;

    float4 dot[4];
    #pragma unroll
    for (int s = 0; s < 4; ++s) dot[s] = make_float4(0.f, 0.f, 0.f, 0.f);
    float cs[8];
    #pragma unroll
    for (int j = 0; j < 8; ++j) cs[j] = 0.f;

    #pragma unroll
    for (int j = 0; j < 8; ++j) {
        const float w = sw[cw * 8 + j];
        const float* xc = xb + (size_t)j * HWq;
        #pragma unroll
        for (int s = 0; s < 4; ++s) {
            const float4 v = *reinterpret_cast<const float4*>(xc + s * 32);
            dot[s].x = fmaf(v.x, w, dot[s].x);
            dot[s].y = fmaf(v.y, w, dot[s].y);
            dot[s].z = fmaf(v.z, w, dot[s].z);
            dot[s].w = fmaf(v.w, w, dot[s].w);
            cs[j] += (v.x + v.y) + (v.z + v.w);
        }
    }

    #pragma unroll
    for (int j = 0; j < 8; ++j) scs[cw * 8 + j][pw] = cs[j];
    #pragma unroll
    for (int s = 0; s < 4; ++s)
        *reinterpret_cast<float4*>(&sdot[s][cw][pw * 4]) = dot[s];
    __syncthreads();

    {
        float s = 0.f;
        #pragma unroll
        for (int k = 0; k < 8; ++k) s += scs[t][k];
        g_csum[((size_t)b * CHUNKS + chunk) * Cq + t] = s;
    }

    if (t < 128) {
        const int s = t >> 5, q = t & 31;
        float d = 0.f;
        #pragma unroll
        for (int k = 0; k < 32; ++k) d += sdot[s][k][q];
        out[(size_t)b * 4 * HWq + (size_t)chunk * 128 + t] = gelu_exact(d);
    }

    // ---- fused pooling: last block of this sample reduces csum -> g_pt ----
    __threadfence();
    __syncthreads();
    if (t == 0) {
        const int old = atomicAdd(&g_pcnt[b], 1);
        if (old == CHUNKS - 1) s_last = 1;
    }
    __syncthreads();
    if (!s_last) return;
    __threadfence();   // acquire all csum writes for sample b

    {
        const float* cs2 = g_csum + (size_t)b * CHUNKS * Cq + t;
        float s = 0.f;
        #pragma unroll 8
        for (int k = 0; k < CHUNKS; ++k) s += cs2[(size_t)k * Cq];
        g_pt[t * Bq + b] = s * (1.0f / (float)HWq);
    }
    __syncthreads();
    if (t == 0) atomicExch(&g_pcnt[b], 0);   // reset for next graph replay
}

// ---------------------------------------------------------------------------
// KPROJ (R13-proven): 24 blocks x 256; block = 16 of 384 columns.
// ---------------------------------------------------------------------------
__global__ __launch_bounds__(256) void kproj(
    const float* __restrict__ Wg, const float* __restrict__ bg,
    const float* __restrict__ Wt, const float* __restrict__ bt,
    const float* __restrict__ Wp, const float* __restrict__ bp)
{
    __shared__ float sp_t[Cq * Bq];    // 16 KB [i][b]
    __shared__ float swt[16][Cq];      // 16 KB
    __shared__ float sb[16];

    const int t    = threadIdx.x;
    const int col0 = blockIdx.x * 16;

    #pragma unroll
    for (int j = 0; j < 4; ++j)
        reinterpret_cast<float4*>(sp_t)[j * 256 + t] =
            reinterpret_cast<const float4*>(g_pt)[j * 256 + t];

    #pragma unroll
    for (int j = 0; j < 4; ++j) {
        const int id = j * 256 + t;
        const int r  = id >> 6;
        const int c4 = id & 63;
        const int col = col0 + r;
        const int cg  = col >> 7;
        const int lc  = col & 127;
        const float* Wrow = (cg == 0) ? (Wg + (size_t)lc * Cq)
                          : (cg == 1) ? (Wt + (size_t)lc * Cq)
                                      : (Wp + (size_t)lc * Cq);
        reinterpret_cast<float4*>(&swt[r][0])[c4] =
            reinterpret_cast<const float4*>(Wrow)[c4];
    }
    if (t < 16) {
        const int col = col0 + t;
        const int cg  = col >> 7;
        const int lc  = col & 127;
        sb[t] = (cg == 0) ? bg[lc] : (cg == 1) ? bt[lc] : bp[lc];
    }
    __syncthreads();

    const int b    = t & 15;
    const int slot = t >> 4;
    float a0 = 0.f, a1 = 0.f, a2 = 0.f, a3 = 0.f;
    #pragma unroll 8
    for (int i = 0; i < Cq; i += 4) {
        a0 = fmaf(swt[slot][i + 0], sp_t[(i + 0) * Bq + b], a0);
        a1 = fmaf(swt[slot][i + 1], sp_t[(i + 1) * Bq + b], a1);
        a2 = fmaf(swt[slot][i + 2], sp_t[(i + 2) * Bq + b], a2);
        a3 = fmaf(swt[slot][i + 3], sp_t[(i + 3) * Bq + b], a3);
    }
    g_gtp[(col0 + slot) * Bq + b] = ((a0 + a1) + (a2 + a3)) + sb[slot];
}

// ---------------------------------------------------------------------------
// KWY: 16 blocks x 256; block = 16 Wz columns. Parallelized f (R14 body,
//   without BN tail).
// ---------------------------------------------------------------------------
__global__ __launch_bounds__(256) void kwy(
    const float* __restrict__ Wf, const float* __restrict__ bf,
    const float* __restrict__ Wz, const float* __restrict__ bz)
{
    __shared__ float sg_t[INTERq * Bq];      // 8 KB
    __shared__ float stp [2 * INTERq * Bq];  // 16 KB
    __shared__ float swz[16][INTERq];        // 8 KB
    __shared__ float swf[2 * INTERq];        // 1 KB
    __shared__ float sfp[16][16];
    __shared__ float sf[Bq];
    __shared__ float sbz[16];

    const int t    = threadIdx.x;
    const int col0 = blockIdx.x * 16;
    const int b    = t & 15;
    const int slot = t >> 4;

    #pragma unroll
    for (int j = 0; j < 2; ++j)
        reinterpret_cast<float4*>(sg_t)[j * 256 + t] =
            reinterpret_cast<const float4*>(g_gtp)[j * 256 + t];
    #pragma unroll
    for (int j = 0; j < 4; ++j)
        reinterpret_cast<float4*>(stp)[j * 256 + t] =
            reinterpret_cast<const float4*>(g_gtp + 2048)[j * 256 + t];
    #pragma unroll
    for (int j = 0; j < 2; ++j) {
        const int id = j * 256 + t;
        const int r  = id >> 5;
        const int c4 = id & 31;
        reinterpret_cast<float4*>(&swz[r][0])[c4] =
            reinterpret_cast<const float4*>(Wz + (size_t)(col0 + r) * INTERq)[c4];
    }
    swf[t] = Wf[t];
    if (t < 16) sbz[t] = bz[col0 + t];
    __syncthreads();

    {
        float a = 0.f;
        #pragma unroll
        for (int i = 0; i < 16; ++i) {
            const int e = slot * 16 + i;
            a = fmaf(stp[e * Bq + b], swf[e], a);
        }
        sfp[slot][b] = a;
    }
    __syncthreads();
    if (t < 16) {
        float s0 = 0.f, s1 = 0.f;
        #pragma unroll
        for (int k = 0; k < 16; k += 2) { s0 += sfp[k][t]; s1 += sfp[k + 1][t]; }
        sf[t] = fmaxf(s0 + s1 + bf[0], 0.f);
    }
    __syncthreads();

    float a0 = 0.f, a1 = 0.f, a2 = 0.f, a3 = 0.f;
    #pragma unroll 8
    for (int i = 0; i < INTERq; i += 4) {
        a0 = fmaf(swz[slot][i + 0], sg_t[(i + 0) * Bq + b], a0);
        a1 = fmaf(swz[slot][i + 1], sg_t[(i + 1) * Bq + b], a1);
        a2 = fmaf(swz[slot][i + 2], sg_t[(i + 2) * Bq + b], a2);
        a3 = fmaf(swz[slot][i + 3], sg_t[(i + 3) * Bq + b], a3);
    }
    g_wyt[(col0 + slot) * Bq + b] = fmaf(sf[b], ((a0 + a1) + (a2 + a3)), sbz[slot]);
}

// ---------------------------------------------------------------------------
// KGATHER_BN: 48 blocks x 1024. Block 0 runs BN+top-3 as a prologue and
//   raises g_flag; all blocks then gather. Flags self-reset (last gatherer).
// ---------------------------------------------------------------------------
__global__ __launch_bounds__(1024) void kgather_bn(const float* __restrict__ x,
                                                   const float* __restrict__ gamma,
                                                   const float* __restrict__ beta,
                                                   float* __restrict__ out) {
    __shared__ float sz[Bq * Cq];   // 16 KB (block 0 only)
    const int bid = blockIdx.x;
    const int t   = threadIdx.x;

    if (bid == 0) {
        if (t < Cq) {
            const int c = t;
            float vals[Bq];
            const float4* w4 = reinterpret_cast<const float4*>(g_wyt + c * Bq);
            const float4* p4 = reinterpret_cast<const float4*>(g_pt  + c * Bq);
            #pragma unroll
            for (int k = 0; k < 4; ++k) {
                const float4 v = w4[k];
                vals[k * 4 + 0] = v.x; vals[k * 4 + 1] = v.y;
                vals[k * 4 + 2] = v.z; vals[k * 4 + 3] = v.w;
            }
            float m = 0.f;
            #pragma unroll
            for (int bb = 0; bb < Bq; ++bb) m += vals[bb];
            m *= (1.0f / (float)Bq);
            float var = 0.f;
            #pragma unroll
            for (int bb = 0; bb < Bq; ++bb) { const float d = vals[bb] - m; var = fmaf(d, d, var); }
            var *= (1.0f / (float)Bq);
            const float inv = rsqrtf(var + 1e-5f);
            const float ga = gamma[c], be = beta[c];
            #pragma unroll
            for (int k = 0; k < 4; ++k) {
                const float4 p = p4[k];
                sz[(k * 4 + 0) * Cq + c] = fmaf(ga * (vals[k * 4 + 0] - m), inv, be) + p.x;
                sz[(k * 4 + 1) * Cq + c] = fmaf(ga * (vals[k * 4 + 1] - m), inv, be) + p.y;
                sz[(k * 4 + 2) * Cq + c] = fmaf(ga * (vals[k * 4 + 2] - m), inv, be) + p.z;
                sz[(k * 4 + 3) * Cq + c] = fmaf(ga * (vals[k * 4 + 3] - m), inv, be) + p.w;
            }
        }
        __syncthreads();
        if (t < 512) {
            const int warp = t >> 5;
            const int lane = t & 31;
            float v[8];
            const int base = warp * Cq;
            #pragma unroll
            for (int k = 0; k < 8; ++k) v[k] = sz[base + k * 32 + lane];

            for (int j = 0; j < 3; ++j) {
                float bv = -INFINITY;
                int   bi = 0x7fffffff;
                #pragma unroll
                for (int k = 0; k < 8; ++k) {
                    const int idx = k * 32 + lane;
                    if (v[k] > bv) { bv = v[k]; bi = idx; }
                }
                #pragma unroll
                for (int off = 16; off > 0; off >>= 1) {
                    const float ov = __shfl_down_sync(0xffffffffu, bv, off);
                    const int   oi = __shfl_down_sync(0xffffffffu, bi, off);
                    if (ov > bv || (ov == bv && oi < bi)) { bv = ov; bi = oi; }
                }
                bi = __shfl_sync(0xffffffffu, bi, 0);
                if (lane == 0) g_idx[warp * 3 + j] = bi;
                const int kk = bi >> 5;
                if ((bi & 31) == lane) {
                    #pragma unroll
                    for (int k = 0; k < 8; ++k) if (k == kk) v[k] = -INFINITY;
                }
            }
        }
        __syncthreads();
        if (t == 0) { __threadfence(); atomicExch(&g_flag, 1); }
    }

    // all blocks: wait for top-3, then gather
    if (t == 0) {
        while (atomicAdd(&g_flag, 0) == 0) { __nanosleep(32); }
        __threadfence();
    }
    __syncthreads();

    const int b = bid / 3, j = bid % 3;
    const int ch = g_idx[b * 3 + j];
    const float* src = x + ((size_t)b * Cq + ch) * HWq;
    float* dst = out + ((size_t)b * 4 + 1 + j) * HWq;
    const float4 v0 = *reinterpret_cast<const float4*>(src + t * 4);
    const float4 v1 = *reinterpret_cast<const float4*>(src + 4096 + t * 4);
    const float4 v2 = *reinterpret_cast<const float4*>(src + 8192 + t * 4);
    const float4 v3 = *reinterpret_cast<const float4*>(src + 12288 + t * 4);
    *reinterpret_cast<float4*>(dst + t * 4)         = v0;
    *reinterpret_cast<float4*>(dst + 4096 + t * 4)  = v1;
    *reinterpret_cast<float4*>(dst + 8192 + t * 4)  = v2;
    *reinterpret_cast<float4*>(dst + 12288 + t * 4) = v3;

    // self-reset flags for the next graph replay
    __syncthreads();
    if (t == 0) {
        const int old = atomicAdd(&g_fin, 1);
        if (old == 47) { atomicExch(&g_fin, 0); atomicExch(&g_flag, 0); }
    }
}

extern "C" void kernel_launch(void* const* d_in, const int* in_sizes, int n_in,
                              void* d_out, int out_size) {
    const float* x     = (const float*)d_in[0];
    const float* Wg    = (const float*)d_in[1];
    const float* bg    = (const float*)d_in[2];
    const float* Wt    = (const float*)d_in[3];
    const float* bt    = (const float*)d_in[4];
    const float* Wp    = (const float*)d_in[5];
    const float* bp    = (const float*)d_in[6];
    const float* Wf    = (const float*)d_in[7];
    const float* bf    = (const float*)d_in[8];
    const float* Wz    = (const float*)d_in[9];
    const float* bz    = (const float*)d_in[10];
    const float* gamma = (const float*)d_in[11];
    const float* beta  = (const float*)d_in[12];
    const float* W3    = (const float*)d_in[13];
    float* out = (float*)d_out;

    k1_stream<<<Bq * CHUNKS, 256>>>(x, W3, out);
    kproj<<<24, 256>>>(Wg, bg, Wt, bt, Wp, bp);
    kwy<<<Bq, 256>>>(Wf, bf, Wz, bz);
    kgather_bn<<<Bq * 3, 1024>>>(x, gamma, beta, out);
}

// round 17
// speedup vs baseline: 1.1307x; 1.1307x over previous
#include <cuda_runtime.h>
#include <cstdint>
#include <math.h>

#define Bq     16
#define Cq     256
#define HWq    16384
#define INTERq 128
#define CHUNKS 128

// scratch
__device__ float g_csum[Bq * CHUNKS * Cq];  // [b][chunk][c] (2 MB)
__device__ float g_pt  [Cq * Bq];           // pooled means [c][b]
__device__ float g_gtp [384 * Bq];          // proj outputs [col][b]: g|theta|phi
__device__ float g_wyt [Cq * Bq];           // pre-BN activations [c][b]
__device__ int   g_idx [Bq * 3];
__device__ int   g_done;                    // kwy completion counter

__device__ __forceinline__ float gelu_exact(float v) {
    return 0.5f * v * (1.0f + erff(v * 0.70710678118654752f));
}

// ---------------------------------------------------------------------------
// K1 (R4-exact, proven 45.6us @ 75.8% DRAM).
// ---------------------------------------------------------------------------
__global__ __launch_bounds__(256) void k1_stream(const float* __restrict__ x,
                                                 const float* __restrict__ W3,
                                                 float* __restrict__ out) {
    __shared__ float sw[Cq];
    __shared__ float scs[Cq][8];
    __shared__ float sdot[4][32][32];

    const int b     = blockIdx.x >> 7;
    const int chunk = blockIdx.x & 127;
    const int t  = threadIdx.x;
    const int cw = t >> 3;
    const int pw = t & 7;

    for (int i = t; i < Cq; i += 256) sw[i] = W3[i];
    __syncthreads();

    const float* xb = x + ((size_t)b * Cq + (size_t)cw * 8) * HWq
                        + (size_t)chunk * 128 + (size_t)pw * 4;

    float4 dot[4];
    #pragma unroll
    for (int s = 0; s < 4; ++s) dot[s] = make_float4(0.f, 0.f, 0.f, 0.f);
    float cs[8];
    #pragma unroll
    for (int j = 0; j < 8; ++j) cs[j] = 0.f;

    #pragma unroll
    for (int j = 0; j < 8; ++j) {
        const float w = sw[cw * 8 + j];
        const float* xc = xb + (size_t)j * HWq;
        #pragma unroll
        for (int s = 0; s < 4; ++s) {
            const float4 v = *reinterpret_cast<const float4*>(xc + s * 32);
            dot[s].x = fmaf(v.x, w, dot[s].x);
            dot[s].y = fmaf(v.y, w, dot[s].y);
            dot[s].z = fmaf(v.z, w, dot[s].z);
            dot[s].w = fmaf(v.w, w, dot[s].w);
            cs[j] += (v.x + v.y) + (v.z + v.w);
        }
    }

    #pragma unroll
    for (int j = 0; j < 8; ++j) scs[cw * 8 + j][pw] = cs[j];
    #pragma unroll
    for (int s = 0; s < 4; ++s)
        *reinterpret_cast<float4*>(&sdot[s][cw][pw * 4]) = dot[s];
    __syncthreads();

    {
        float s = 0.f;
        #pragma unroll
        for (int k = 0; k < 8; ++k) s += scs[t][k];
        g_csum[((size_t)b * CHUNKS + chunk) * Cq + t] = s;
    }

    if (t < 128) {
        const int s = t >> 5, q = t & 31;
        float d = 0.f;
        #pragma unroll
        for (int k = 0; k < 32; ++k) d += sdot[s][k][q];
        out[(size_t)b * 4 * HWq + (size_t)chunk * 128 + t] = gelu_exact(d);
    }
}

// ---------------------------------------------------------------------------
// KPOOL (PDL): waits for k1, then R12-proven pool body.
// ---------------------------------------------------------------------------
__global__ __launch_bounds__(1024) void kpool() {
    __shared__ float part[4][Cq];
    const int b  = blockIdx.x;
    const int t  = threadIdx.x;
    const int c  = t & 255;
    const int qq = t >> 8;

    cudaGridDependencySynchronize();

    const float* cs = g_csum + (size_t)b * CHUNKS * Cq + (size_t)qq * 32 * Cq + c;
    float s = 0.f;
    #pragma unroll 8
    for (int k = 0; k < 32; ++k) s += cs[(size_t)k * Cq];
    part[qq][c] = s;
    __syncthreads();
    if (t < Cq)
        g_pt[t * Bq + b] = ((part[0][t] + part[1][t]) + (part[2][t] + part[3][t]))
                         * (1.0f / (float)HWq);
}

// ---------------------------------------------------------------------------
// KPROJ (PDL): stages weights BEFORE gridDepSync (overlaps with kpool),
//   then stages g_pt and runs the R13-proven dot body. Resets g_done.
// ---------------------------------------------------------------------------
__global__ __launch_bounds__(256) void kproj(
    const float* __restrict__ Wg, const float* __restrict__ bg,
    const float* __restrict__ Wt, const float* __restrict__ bt,
    const float* __restrict__ Wp, const float* __restrict__ bp)
{
    __shared__ float sp_t[Cq * Bq];    // 16 KB [i][b]
    __shared__ float swt[16][Cq];      // 16 KB
    __shared__ float sb[16];

    const int t    = threadIdx.x;
    const int col0 = blockIdx.x * 16;

    if (blockIdx.x == 0 && t == 0) g_done = 0;

    // --- independent staging: weights + biases (overlaps with kpool) ---
    #pragma unroll
    for (int j = 0; j < 4; ++j) {
        const int id = j * 256 + t;
        const int r  = id >> 6;
        const int c4 = id & 63;
        const int col = col0 + r;
        const int cg  = col >> 7;
        const int lc  = col & 127;
        const float* Wrow = (cg == 0) ? (Wg + (size_t)lc * Cq)
                          : (cg == 1) ? (Wt + (size_t)lc * Cq)
                                      : (Wp + (size_t)lc * Cq);
        reinterpret_cast<float4*>(&swt[r][0])[c4] =
            reinterpret_cast<const float4*>(Wrow)[c4];
    }
    if (t < 16) {
        const int col = col0 + t;
        const int cg  = col >> 7;
        const int lc  = col & 127;
        sb[t] = (cg == 0) ? bg[lc] : (cg == 1) ? bt[lc] : bp[lc];
    }

    cudaGridDependencySynchronize();

    // --- dependent staging: pooled means ---
    #pragma unroll
    for (int j = 0; j < 4; ++j)
        reinterpret_cast<float4*>(sp_t)[j * 256 + t] =
            reinterpret_cast<const float4*>(g_pt)[j * 256 + t];
    __syncthreads();

    const int b    = t & 15;
    const int slot = t >> 4;
    float a0 = 0.f, a1 = 0.f, a2 = 0.f, a3 = 0.f;
    #pragma unroll 8
    for (int i = 0; i < Cq; i += 4) {
        a0 = fmaf(swt[slot][i + 0], sp_t[(i + 0) * Bq + b], a0);
        a1 = fmaf(swt[slot][i + 1], sp_t[(i + 1) * Bq + b], a1);
        a2 = fmaf(swt[slot][i + 2], sp_t[(i + 2) * Bq + b], a2);
        a3 = fmaf(swt[slot][i + 3], sp_t[(i + 3) * Bq + b], a3);
    }
    g_gtp[(col0 + slot) * Bq + b] = ((a0 + a1) + (a2 + a3)) + sb[slot];
}

// ---------------------------------------------------------------------------
// KWY_BN (PDL): stages Wz/Wf/bz BEFORE gridDepSync (overlaps with kproj),
//   then R14-proven body: parallel f, dot, last-block BN + top-3.
// ---------------------------------------------------------------------------
__global__ __launch_bounds__(256) void kwy_bn(
    const float* __restrict__ Wf, const float* __restrict__ bf,
    const float* __restrict__ Wz, const float* __restrict__ bz,
    const float* __restrict__ gamma, const float* __restrict__ beta)
{
    __shared__ float sg_t[INTERq * Bq];      // 8 KB
    __shared__ float stp [2 * INTERq * Bq];  // 16 KB; reused as sz
    __shared__ float swz[16][INTERq];        // 8 KB
    __shared__ float swf[2 * INTERq];        // 1 KB
    __shared__ float sfp[16][16];
    __shared__ float sf[Bq];
    __shared__ float sbz[16];
    __shared__ int   s_last;

    const int t    = threadIdx.x;
    const int col0 = blockIdx.x * 16;
    const int b    = t & 15;
    const int slot = t >> 4;

    if (t == 0) s_last = 0;

    // --- independent staging (overlaps with kproj) ---
    #pragma unroll
    for (int j = 0; j < 2; ++j) {
        const int id = j * 256 + t;
        const int r  = id >> 5;
        const int c4 = id & 31;
        reinterpret_cast<float4*>(&swz[r][0])[c4] =
            reinterpret_cast<const float4*>(Wz + (size_t)(col0 + r) * INTERq)[c4];
    }
    swf[t] = Wf[t];
    if (t < 16) sbz[t] = bz[col0 + t];

    cudaGridDependencySynchronize();

    // --- dependent staging ---
    #pragma unroll
    for (int j = 0; j < 2; ++j)
        reinterpret_cast<float4*>(sg_t)[j * 256 + t] =
            reinterpret_cast<const float4*>(g_gtp)[j * 256 + t];
    #pragma unroll
    for (int j = 0; j < 4; ++j)
        reinterpret_cast<float4*>(stp)[j * 256 + t] =
            reinterpret_cast<const float4*>(g_gtp + 2048)[j * 256 + t];
    __syncthreads();

    {
        float a = 0.f;
        #pragma unroll
        for (int i = 0; i < 16; ++i) {
            const int e = slot * 16 + i;
            a = fmaf(stp[e * Bq + b], swf[e], a);
        }
        sfp[slot][b] = a;
    }
    __syncthreads();
    if (t < 16) {
        float s0 = 0.f, s1 = 0.f;
        #pragma unroll
        for (int k = 0; k < 16; k += 2) { s0 += sfp[k][t]; s1 += sfp[k + 1][t]; }
        sf[t] = fmaxf(s0 + s1 + bf[0], 0.f);
    }

    float a0 = 0.f, a1 = 0.f, a2 = 0.f, a3 = 0.f;
    #pragma unroll 8
    for (int i = 0; i < INTERq; i += 4) {
        a0 = fmaf(swz[slot][i + 0], sg_t[(i + 0) * Bq + b], a0);
        a1 = fmaf(swz[slot][i + 1], sg_t[(i + 1) * Bq + b], a1);
        a2 = fmaf(swz[slot][i + 2], sg_t[(i + 2) * Bq + b], a2);
        a3 = fmaf(swz[slot][i + 3], sg_t[(i + 3) * Bq + b], a3);
    }
    __syncthreads();
    g_wyt[(col0 + slot) * Bq + b] = fmaf(sf[b], ((a0 + a1) + (a2 + a3)), sbz[slot]);

    // ---- last-block-done: BN + top-3 (R14-proven) ----
    __threadfence();
    __syncthreads();
    if (t == 0) {
        const int old = atomicAdd(&g_done, 1);
        if (old == 15) s_last = 1;
    }
    __syncthreads();
    if (!s_last) return;
    __threadfence();

    float* sz = stp;

    {
        const int c = t;
        float vals[Bq];
        const float4* w4 = reinterpret_cast<const float4*>(g_wyt + c * Bq);
        const float4* p4 = reinterpret_cast<const float4*>(g_pt  + c * Bq);
        #pragma unroll
        for (int k = 0; k < 4; ++k) {
            const float4 v = w4[k];
            vals[k * 4 + 0] = v.x; vals[k * 4 + 1] = v.y;
            vals[k * 4 + 2] = v.z; vals[k * 4 + 3] = v.w;
        }
        float m = 0.f;
        #pragma unroll
        for (int bb = 0; bb < Bq; ++bb) m += vals[bb];
        m *= (1.0f / (float)Bq);
        float var = 0.f;
        #pragma unroll
        for (int bb = 0; bb < Bq; ++bb) { const float d = vals[bb] - m; var = fmaf(d, d, var); }
        var *= (1.0f / (float)Bq);
        const float inv = rsqrtf(var + 1e-5f);
        const float ga = gamma[c], be = beta[c];
        #pragma unroll
        for (int k = 0; k < 4; ++k) {
            const float4 p = p4[k];
            sz[(k * 4 + 0) * Cq + c] = fmaf(ga * (vals[k * 4 + 0] - m), inv, be) + p.x;
            sz[(k * 4 + 1) * Cq + c] = fmaf(ga * (vals[k * 4 + 1] - m), inv, be) + p.y;
            sz[(k * 4 + 2) * Cq + c] = fmaf(ga * (vals[k * 4 + 2] - m), inv, be) + p.z;
            sz[(k * 4 + 3) * Cq + c] = fmaf(ga * (vals[k * 4 + 3] - m), inv, be) + p.w;
        }
    }
    __syncthreads();

    {
        const int warp = t >> 5;
        const int lane = t & 31;
        #pragma unroll
        for (int sb2 = 0; sb2 < 2; ++sb2) {
            const int smp = warp + sb2 * 8;
            float v[8];
            const int base = smp * Cq;
            #pragma unroll
            for (int k = 0; k < 8; ++k) v[k] = sz[base + k * 32 + lane];

            for (int j = 0; j < 3; ++j) {
                float bv = -INFINITY;
                int   bi = 0x7fffffff;
                #pragma unroll
                for (int k = 0; k < 8; ++k) {
                    const int idx = k * 32 + lane;
                    if (v[k] > bv) { bv = v[k]; bi = idx; }
                }
                #pragma unroll
                for (int off = 16; off > 0; off >>= 1) {
                    const float ov = __shfl_down_sync(0xffffffffu, bv, off);
                    const int   oi = __shfl_down_sync(0xffffffffu, bi, off);
                    if (ov > bv || (ov == bv && oi < bi)) { bv = ov; bi = oi; }
                }
                bi = __shfl_sync(0xffffffffu, bi, 0);
                if (lane == 0) g_idx[smp * 3 + j] = bi;
                const int kk = bi >> 5;
                if ((bi & 31) == lane) {
                    #pragma unroll
                    for (int k = 0; k < 8; ++k) if (k == kk) v[k] = -INFINITY;
                }
            }
        }
    }
}

// ---------------------------------------------------------------------------
// KGATHER (PDL): address setup overlaps; reads g_idx after gridDepSync.
// ---------------------------------------------------------------------------
__global__ __launch_bounds__(1024) void kgather(const float* __restrict__ x,
                                                float* __restrict__ out) {
    const int b = blockIdx.x / 3, j = blockIdx.x % 3;
    const int t = threadIdx.x;
    float* dst = out + ((size_t)b * 4 + 1 + j) * HWq;

    cudaGridDependencySynchronize();

    const int ch = g_idx[b * 3 + j];
    const float* src = x + ((size_t)b * Cq + ch) * HWq;
    const float4 v0 = *reinterpret_cast<const float4*>(src + t * 4);
    const float4 v1 = *reinterpret_cast<const float4*>(src + 4096 + t * 4);
    const float4 v2 = *reinterpret_cast<const float4*>(src + 8192 + t * 4);
    const float4 v3 = *reinterpret_cast<const float4*>(src + 12288 + t * 4);
    *reinterpret_cast<float4*>(dst + t * 4)         = v0;
    *reinterpret_cast<float4*>(dst + 4096 + t * 4)  = v1;
    *reinterpret_cast<float4*>(dst + 8192 + t * 4)  = v2;
    *reinterpret_cast<float4*>(dst + 12288 + t * 4) = v3;
}

// helper: PDL launch
template <typename F, typename... Args>
static inline void launch_pdl(F func, dim3 grid, dim3 block, Args... args) {
    cudaLaunchConfig_t cfg = {};
    cfg.gridDim = grid;
    cfg.blockDim = block;
    cfg.dynamicSmemBytes = 0;
    cfg.stream = 0;
    cudaLaunchAttribute attr[1];
    attr[0].id = cudaLaunchAttributeProgrammaticStreamSerialization;
    attr[0].val.programmaticStreamSerializationAllowed = 1;
    cfg.attrs = attr;
    cfg.numAttrs = 1;
    cudaLaunchKernelEx(&cfg, func, args...);
}

extern "C" void kernel_launch(void* const* d_in, const int* in_sizes, int n_in,
                              void* d_out, int out_size) {
    const float* x     = (const float*)d_in[0];
    const float* Wg    = (const float*)d_in[1];
    const float* bg    = (const float*)d_in[2];
    const float* Wt    = (const float*)d_in[3];
    const float* bt    = (const float*)d_in[4];
    const float* Wp    = (const float*)d_in[5];
    const float* bp    = (const float*)d_in[6];
    const float* Wf    = (const float*)d_in[7];
    const float* bf    = (const float*)d_in[8];
    const float* Wz    = (const float*)d_in[9];
    const float* bz    = (const float*)d_in[10];
    const float* gamma = (const float*)d_in[11];
    const float* beta  = (const float*)d_in[12];
    const float* W3    = (const float*)d_in[13];
    float* out = (float*)d_out;

    k1_stream<<<Bq * CHUNKS, 256>>>(x, W3, out);
    launch_pdl(kpool,   dim3(Bq),      dim3(1024));
    launch_pdl(kproj,   dim3(24),      dim3(256), Wg, bg, Wt, bt, Wp, bp);
    launch_pdl(kwy_bn,  dim3(Bq),      dim3(256), Wf, bf, Wz, bz, gamma, beta);
    launch_pdl(kgather, dim3(Bq * 3),  dim3(1024), x, out);
}